// round 16
// baseline (speedup 1.0000x reference)
#include <cuda_runtime.h>
#include <cuda_bf16.h>
#include <cuda_fp16.h>
#include <cstdint>

#define BB   32
#define NN   512
#define FIN  128
#define FH   64
#define NH   8
#define FC   512
#define CC   16
#define LALPHA 0.2f
#define JB   128
#define ONE2 0x3C003C00u
#define PROJ_BLOCKS 2048
#define PACK_BLOCKS 2048

// ---------------- device scratch ----------------
__device__ unsigned short g_hfeat16[BB*NN*FC];   // f16 projected features (V)
__device__ float g_xcat [BB*NN*FC];
__device__ unsigned int g_mask[BB*NN*(NN/32)];
__device__ float g_f1[NH*BB*NN], g_f2[NH*BB*NN];
__device__ unsigned g_f2maxu[NH*BB];      // zero-init; atomicMax idempotent across replays
__device__ unsigned g_f2bmaxu[BB];
__device__ int   g_rowempty[BB*NN];
__device__ float g_h2[BB*NN*CC];
__device__ float g_f1b[BB*NN], g_f2b[BB*NN];

// ---------------- helpers ----------------
__device__ __forceinline__ unsigned long long pack2(float x, float y){
    unsigned long long r; asm("mov.b64 %0, {%1, %2};" : "=l"(r) : "f"(x), "f"(y)); return r;
}
__device__ __forceinline__ float2 unpack2(unsigned long long v){
    float2 r; asm("mov.b64 {%0, %1}, %2;" : "=f"(r.x), "=f"(r.y) : "l"(v)); return r;
}
__device__ __forceinline__ unsigned long long fma2(unsigned long long a, unsigned long long b, unsigned long long c){
    unsigned long long d; asm("fma.rn.f32x2 %0, %1, %2, %3;" : "=l"(d) : "l"(a), "l"(b), "l"(c)); return d;
}
__device__ __forceinline__ unsigned cvt2h(float vlo, float vhi){
    __half2 h = __floats2half2_rn(vlo, vhi);
    return *(unsigned*)&h;
}
__device__ __forceinline__ unsigned sm32(const void* p){
    unsigned a; asm("{ .reg .u64 t; cvta.to.shared.u64 t, %1; cvt.u32.u64 %0, t; }" : "=r"(a) : "l"(p)); return a;
}
#define SWZ(o) ((o) ^ (((o) >> 3) & 0x70))

__device__ __forceinline__ unsigned fenc(float f){
    unsigned u = __float_as_uint(f);
    return ((int)u < 0) ? ~u : (u | 0x80000000u);
}
__device__ __forceinline__ float fdec(unsigned u){
    unsigned v = (u & 0x80000000u) ? (u & 0x7fffffffu) : ~u;
    return __uint_as_float(v);
}

__device__ __forceinline__ void ldsm4(unsigned& r0, unsigned& r1, unsigned& r2, unsigned& r3, unsigned addr){
    asm volatile("ldmatrix.sync.aligned.m8n8.x4.shared.b16 {%0,%1,%2,%3}, [%4];"
        : "=r"(r0), "=r"(r1), "=r"(r2), "=r"(r3) : "r"(addr));
}
__device__ __forceinline__ void ldsm4t(unsigned& r0, unsigned& r1, unsigned& r2, unsigned& r3, unsigned addr){
    asm volatile("ldmatrix.sync.aligned.m8n8.x4.trans.shared.b16 {%0,%1,%2,%3}, [%4];"
        : "=r"(r0), "=r"(r1), "=r"(r2), "=r"(r3) : "r"(addr));
}
__device__ __forceinline__ void mma16816h(float* c, const unsigned* a, unsigned b0, unsigned b1){
    asm volatile("mma.sync.aligned.m16n8k16.row.col.f32.f16.f16.f32 "
        "{%0,%1,%2,%3}, {%4,%5,%6,%7}, {%8,%9}, {%0,%1,%2,%3};"
        : "+f"(c[0]), "+f"(c[1]), "+f"(c[2]), "+f"(c[3])
        : "r"(a[0]), "r"(a[1]), "r"(a[2]), "r"(a[3]), "r"(b0), "r"(b1));
}

// ---------------- kernel 1: fused mma proj1 + adj pack (heterogeneous) ---------
__global__ __launch_bounds__(256) void fused_pack_proj_kernel(
        const int* __restrict__ adj,
        const float* __restrict__ X, const float* __restrict__ Wh,
        const float* __restrict__ a1h, const float* __restrict__ a2h){
    __shared__ __align__(128) unsigned short Xhi[64*64], Xlo[64*64];
    __shared__ __align__(128) unsigned short Whi[64*64], Wlo[64*64];
    __shared__ float ps1[4][2][16], ps2[4][2][16];
    __shared__ float sm2[2];
    const int tid = threadIdx.x;

    if (blockIdx.x >= PROJ_BLOCKS){
        int gt = (blockIdx.x - PROJ_BLOCKS) * 256 + tid;
        const int4* src = (const int4*)adj + (size_t)gt*4;
        unsigned x = 0;
#pragma unroll
        for (int i = 0; i < 4; i++){
            int4 v = src[i];
            unsigned bi = (unsigned)(v.x > 0) | ((unsigned)(v.y > 0) << 1)
                        | ((unsigned)(v.z > 0) << 2) | ((unsigned)(v.w > 0) << 3);
            x |= bi << (i*4);
        }
        x |= __shfl_down_sync(0xffffffffu, x, 1) << 16;
        if ((tid & 1) == 0) g_mask[gt >> 1] = x;
        return;
    }

    const int pid = blockIdx.x;
    const int m0  = (pid & 255) * 64;
    const int h   = pid >> 8;
    const int lane = tid & 31;
    const int wid  = tid >> 5;
    const int wn   = wid & 1;
    const int wm   = wid >> 1;
    const int g    = lane >> 2;
    const int c    = lane & 3;
    const int jb   = c * 2;

    const unsigned xhi_b = sm32(Xhi), xlo_b = sm32(Xlo);
    const unsigned whi_b = sm32(Whi), wlo_b = sm32(Wlo);

    const int arow  = lane & 15;
    const unsigned aoff0 = (unsigned)((lane >> 4) * 16);
    const unsigned axm   = (unsigned)((arow & 7) << 4);
    const unsigned albase = xlo_b + (unsigned)(((wm*16 + arow)) * 128);
    const int brow = ((lane >> 3) & 1)*8 + (lane & 7);
    const unsigned bxm = (unsigned)((brow & 7) << 4);
    unsigned bboff[2];
#pragma unroll
    for (int np = 0; np < 2; np++){
        unsigned nc2 = (unsigned)((wn*32 + np*16 + (lane >> 4)*8) * 2);
        bboff[np] = (unsigned)(brow*128) + (nc2 ^ bxm);
    }

    float acc[4][4];
#pragma unroll
    for (int i = 0; i < 4; i++){ acc[i][0]=0.f; acc[i][1]=0.f; acc[i][2]=0.f; acc[i][3]=0.f; }

    for (int kc = 0; kc < 2; kc++){
        __syncthreads();
#pragma unroll
        for (int i = 0; i < 4; i++){
            int lin = tid + i*256;
            int row = lin >> 4;
            int kq  = lin & 15;
            float4 v = *(const float4*)&X[(size_t)(m0 + row)*FIN + kc*64 + kq*4];
            unsigned h0 = cvt2h(v.x, v.y);
            unsigned h1 = cvt2h(v.z, v.w);
            float rx = v.x - __half2float(__ushort_as_half((unsigned short)(h0 & 0xffff)));
            float ry = v.y - __half2float(__ushort_as_half((unsigned short)(h0 >> 16)));
            float rz = v.z - __half2float(__ushort_as_half((unsigned short)(h1 & 0xffff)));
            float rw = v.w - __half2float(__ushort_as_half((unsigned short)(h1 >> 16)));
            unsigned l0 = cvt2h(rx, ry);
            unsigned l1 = cvt2h(rz, rw);
            unsigned off = SWZ((unsigned)(row*128 + kq*8));
            *(uint2*)((char*)Xhi + off) = make_uint2(h0, h1);
            *(uint2*)((char*)Xlo + off) = make_uint2(l0, l1);
        }
#pragma unroll
        for (int i = 0; i < 4; i++){
            int lin = tid + i*256;
            int kr = lin >> 4;
            int nq = lin & 15;
            float4 v = *(const float4*)&Wh[(size_t)(h*FIN + kc*64 + kr)*FH + nq*4];
            unsigned h0 = cvt2h(v.x, v.y);
            unsigned h1 = cvt2h(v.z, v.w);
            float rx = v.x - __half2float(__ushort_as_half((unsigned short)(h0 & 0xffff)));
            float ry = v.y - __half2float(__ushort_as_half((unsigned short)(h0 >> 16)));
            float rz = v.z - __half2float(__ushort_as_half((unsigned short)(h1 & 0xffff)));
            float rw = v.w - __half2float(__ushort_as_half((unsigned short)(h1 >> 16)));
            unsigned l0 = cvt2h(rx, ry);
            unsigned l1 = cvt2h(rz, rw);
            unsigned off = SWZ((unsigned)(kr*128 + nq*8));
            *(uint2*)((char*)Whi + off) = make_uint2(h0, h1);
            *(uint2*)((char*)Wlo + off) = make_uint2(l0, l1);
        }
        __syncthreads();

#pragma unroll
        for (int ks = 0; ks < 4; ks++){
            unsigned ahf[4], alf[4];
            unsigned aoff = ((unsigned)(ks*32) + aoff0) ^ axm;
            ldsm4(ahf[0], ahf[1], ahf[2], ahf[3], albase + (xhi_b - xlo_b) + aoff);
            ldsm4(alf[0], alf[1], alf[2], alf[3], albase + aoff);
#pragma unroll
            for (int np = 0; np < 2; np++){
                unsigned bh0, bh1, bh2, bh3, bl0, bl1, bl2, bl3;
                ldsm4t(bh0, bh1, bh2, bh3, whi_b + bboff[np] + (unsigned)(ks*2048));
                ldsm4t(bl0, bl1, bl2, bl3, wlo_b + bboff[np] + (unsigned)(ks*2048));
                mma16816h(acc[2*np],   ahf, bh0, bh1);
                mma16816h(acc[2*np],   ahf, bl0, bl1);
                mma16816h(acc[2*np],   alf, bh0, bh1);
                mma16816h(acc[2*np+1], ahf, bh2, bh3);
                mma16816h(acc[2*np+1], ahf, bl2, bl3);
                mma16816h(acc[2*np+1], alf, bh2, bh3);
            }
        }
    }

    const int rlo = m0 + wm*16 + g;
    const int rhi = rlo + 8;
    float s1lo = 0.f, s2lo = 0.f, s1hi = 0.f, s2hi = 0.f;
#pragma unroll
    for (int nt = 0; nt < 4; nt++){
        int ncol = wn*32 + nt*8 + jb;
        *(unsigned*)&g_hfeat16[(size_t)rlo*FC + h*FH + ncol] = cvt2h(acc[nt][0], acc[nt][1]);
        *(unsigned*)&g_hfeat16[(size_t)rhi*FC + h*FH + ncol] = cvt2h(acc[nt][2], acc[nt][3]);
        float2 a1v = *(const float2*)&a1h[h*FH + ncol];
        float2 a2v = *(const float2*)&a2h[h*FH + ncol];
        s1lo += acc[nt][0]*a1v.x + acc[nt][1]*a1v.y;
        s2lo += acc[nt][0]*a2v.x + acc[nt][1]*a2v.y;
        s1hi += acc[nt][2]*a1v.x + acc[nt][3]*a1v.y;
        s2hi += acc[nt][2]*a2v.x + acc[nt][3]*a2v.y;
    }
#pragma unroll
    for (int o = 1; o <= 2; o <<= 1){
        s1lo += __shfl_xor_sync(0xffffffffu, s1lo, o);
        s2lo += __shfl_xor_sync(0xffffffffu, s2lo, o);
        s1hi += __shfl_xor_sync(0xffffffffu, s1hi, o);
        s2hi += __shfl_xor_sync(0xffffffffu, s2hi, o);
    }
    if (c == 0){
        ps1[wm][wn][g]     = s1lo;  ps2[wm][wn][g]     = s2lo;
        ps1[wm][wn][g + 8] = s1hi;  ps2[wm][wn][g + 8] = s2hi;
    }
    __syncthreads();
    const int b = m0 >> 9;
    float mx = -3.0e38f;
    if (tid < 64){
        int r = tid & 15, wm2 = tid >> 4;
        float s1 = ps1[wm2][0][r] + ps1[wm2][1][r];
        float s2 = ps2[wm2][0][r] + ps2[wm2][1][r];
        int row = m0 + wm2*16 + r;
        int n = row & 511;
        g_f1[(h*BB + b)*NN + n] = s1;
        g_f2[(h*BB + b)*NN + n] = s2;
        mx = s2;
    }
#pragma unroll
    for (int o = 16; o; o >>= 1) mx = fmaxf(mx, __shfl_xor_sync(0xffffffffu, mx, o));
    if (tid < 64 && lane == 0) sm2[wid] = mx;
    __syncthreads();
    if (tid == 0) atomicMax(&g_f2maxu[h*BB + b], fenc(fmaxf(sm2[0], sm2[1])));
}

// ---------------- kernel 2: empty-row flags ----------------
__global__ __launch_bounds__(256) void emptyrow_kernel(){
    int r = blockIdx.x * 256 + threadIdx.x;
    const uint4* p = (const uint4*)&g_mask[r*16];
    uint4 a = p[0], b = p[1], c = p[2], d = p[3];
    unsigned o = a.x|a.y|a.z|a.w|b.x|b.y|b.z|b.w|c.x|c.y|c.z|c.w|d.x|d.y|d.z|d.w;
    g_rowempty[r] = (o == 0u);
}

// ---------------- kernel 3: mma.sync attention L1 (inline exp) ----------------
__global__ __launch_bounds__(256, 3) void mma_attn1_kernel(){
    __shared__ float2 ab[NN];
    __shared__ __align__(128) unsigned short Vh[JB*FH];

    const int tid  = threadIdx.x;
    const int lane = tid & 31;
    const int wid  = tid >> 5;
    const int b = blockIdx.y, h = blockIdx.z;
    const int q0 = blockIdx.x * 128;
    const int g  = lane >> 2;
    const int jb = (lane & 3) * 2;

    {
        float v0 = g_f2[(h*BB + b)*NN + tid];
        float v1 = g_f2[(h*BB + b)*NN + tid + 256];
        ab[tid]       = make_float2(__expf(v0), __expf(LALPHA*v0));
        ab[tid + 256] = make_float2(__expf(v1), __expf(LALPHA*v1));
    }

    const int qlo = q0 + wid*16 + g;
    const int qhi = qlo + 8;
    const float fmx = fdec(g_f2maxu[h*BB + b]);
    const float f1lo = g_f1[(h*BB + b)*NN + qlo];
    const float f1hi = g_f1[(h*BB + b)*NN + qhi];
    float s;
    s = f1lo + fmx; const float Mlo = fmaxf(s, LALPHA*s);
    s = f1hi + fmx; const float Mhi = fmaxf(s, LALPHA*s);
    const float Clo = __expf(f1lo - Mlo), Dlo = __expf(LALPHA*f1lo - Mlo);
    const float Chi = __expf(f1hi - Mhi), Dhi = __expf(LALPHA*f1hi - Mhi);
    const float eflo = g_rowempty[b*NN + qlo] ? 1.f : 0.f;
    const float efhi = g_rowempty[b*NN + qhi] ? 1.f : 0.f;

    const unsigned vh_b = sm32(Vh);
    const unsigned xm  = (unsigned)((lane & 7) << 4);
    const int      jjb = ((lane >> 3) & 1)*8 + (lane & 7);
    unsigned vbase[4];
#pragma unroll
    for (int np = 0; np < 4; np++){
        unsigned nc2 = (unsigned)((np*16 + (lane >> 4)*8) * 2);
        vbase[np] = vh_b + (unsigned)(jjb*128) + (nc2 ^ xm);
    }

    float acc[8][4];
#pragma unroll
    for (int i = 0; i < 8; i++){ acc[i][0]=0.f; acc[i][1]=0.f; acc[i][2]=0.f; acc[i][3]=0.f; }
    float lsum[4] = {0.f, 0.f, 0.f, 0.f};

    for (int t = 0; t < 4; t++){
        const int j0 = t * JB;
        __syncthreads();
#pragma unroll
        for (int i = 0; i < 8; i++){
            int lin = tid + i*256;
            int jj = lin >> 4;
            int f4 = lin & 15;
            uint2 v = *(const uint2*)&g_hfeat16[(size_t)(b*NN + j0 + jj)*FC + h*FH + f4*4];
            unsigned off = SWZ((unsigned)(jj*128 + f4*8));
            *(uint2*)((char*)Vh + off) = v;
        }
        __syncthreads();

        uint4 m4l = *(const uint4*)&g_mask[(b*NN + qlo)*16 + t*4];
        uint4 m4h = *(const uint4*)&g_mask[(b*NN + qhi)*16 + t*4];
        unsigned mwl[4] = {m4l.x >> jb, m4l.y >> jb, m4l.z >> jb, m4l.w >> jb};
        unsigned mwh[4] = {m4h.x >> jb, m4h.y >> jb, m4h.z >> jb, m4h.w >> jb};

#pragma unroll
        for (int kk = 0; kk < 8; kk++){
            float4 u01 = *(const float4*)&ab[j0 + kk*16 + jb];
            float4 u89 = *(const float4*)&ab[j0 + kk*16 + jb + 8];
            unsigned ah[4];
            {
                unsigned w = mwl[kk>>1] >> ((kk&1)<<4);
                float p0 = fmaxf(u01.x*Clo, u01.y*Dlo);
                float p1 = fmaxf(u01.z*Clo, u01.w*Dlo);
                float p8 = fmaxf(u89.x*Clo, u89.y*Dlo);
                float p9 = fmaxf(u89.z*Clo, u89.w*Dlo);
                p0 = (w & 1u)        ? p0 : eflo;
                p1 = (w & 2u)        ? p1 : eflo;
                p8 = ((w >> 8) & 1u) ? p8 : eflo;
                p9 = ((w >> 9) & 1u) ? p9 : eflo;
                ah[0] = cvt2h(p0, p1);
                ah[2] = cvt2h(p8, p9);
            }
            {
                unsigned w = mwh[kk>>1] >> ((kk&1)<<4);
                float p0 = fmaxf(u01.x*Chi, u01.y*Dhi);
                float p1 = fmaxf(u01.z*Chi, u01.w*Dhi);
                float p8 = fmaxf(u89.x*Chi, u89.y*Dhi);
                float p9 = fmaxf(u89.z*Chi, u89.w*Dhi);
                p0 = (w & 1u)        ? p0 : efhi;
                p1 = (w & 2u)        ? p1 : efhi;
                p8 = ((w >> 8) & 1u) ? p8 : efhi;
                p9 = ((w >> 9) & 1u) ? p9 : efhi;
                ah[1] = cvt2h(p0, p1);
                ah[3] = cvt2h(p8, p9);
            }

            mma16816h(lsum, ah, ONE2, ONE2);

#pragma unroll
            for (int np = 0; np < 4; np++){
                unsigned b0, b1, b2, b3;
                ldsm4t(b0, b1, b2, b3, vbase[np] + (unsigned)(kk*2048));
                mma16816h(acc[2*np],   ah, b0, b1);
                mma16816h(acc[2*np+1], ah, b2, b3);
            }
        }
    }

    const float rlo = 1.0f / lsum[0];
    const float rhi = 1.0f / lsum[2];
    float* olo = &g_xcat[(size_t)(b*NN + qlo)*FC + h*FH];
    float* ohi = &g_xcat[(size_t)(b*NN + qhi)*FC + h*FH];
#pragma unroll
    for (int nt = 0; nt < 8; nt++){
        int fo = nt*8 + jb;
        float a0 = acc[nt][0]*rlo, a1 = acc[nt][1]*rlo;
        float a2 = acc[nt][2]*rhi, a3 = acc[nt][3]*rhi;
        float2 u, v;
        u.x = (a0 > 0.f) ? a0 : expm1f(a0);
        u.y = (a1 > 0.f) ? a1 : expm1f(a1);
        v.x = (a2 > 0.f) ? a2 : expm1f(a2);
        v.y = (a3 > 0.f) ? a3 : expm1f(a3);
        *(float2*)&olo[fo] = u;
        *(float2*)&ohi[fo] = v;
    }
}

// ---------------- kernel 4: proj2, grid 256 x (1 row/thread) + FFMA2 -----------
__global__ __launch_bounds__(256) void proj2_kernel(const float* __restrict__ Wout,
                                                    const float* __restrict__ a1o,
                                                    const float* __restrict__ a2o){
    __shared__ float4 ws[FC][4];
    __shared__ float wmax2[8];
    const int tid = threadIdx.x;
#pragma unroll
    for (int i = 0; i < 8; i++)
        ((float4*)ws)[tid + i*256] = ((const float4*)Wout)[tid + i*256];
    __syncthreads();
    const int r  = tid >> 2;
    const int cq = tid & 3;
    const int row = blockIdx.x * 64 + r;

    unsigned long long acc0 = 0ull, acc1 = 0ull;

#pragma unroll 8
    for (int k4 = 0; k4 < FC/4; k4++){
        ulonglong2 wp0 = *(const ulonglong2*)&ws[k4*4+0][cq];
        ulonglong2 wp1 = *(const ulonglong2*)&ws[k4*4+1][cq];
        ulonglong2 wp2 = *(const ulonglong2*)&ws[k4*4+2][cq];
        ulonglong2 wp3 = *(const ulonglong2*)&ws[k4*4+3][cq];
        float4 xv = *(const float4*)&g_xcat[(size_t)row*FC + k4*4];
        unsigned long long ax = pack2(xv.x, xv.x);
        unsigned long long ay = pack2(xv.y, xv.y);
        unsigned long long az = pack2(xv.z, xv.z);
        unsigned long long aw = pack2(xv.w, xv.w);
        acc0 = fma2(ax, wp0.x, acc0);
        acc1 = fma2(ax, wp0.y, acc1);
        acc0 = fma2(ay, wp1.x, acc0);
        acc1 = fma2(ay, wp1.y, acc1);
        acc0 = fma2(az, wp2.x, acc0);
        acc1 = fma2(az, wp2.y, acc1);
        acc0 = fma2(aw, wp3.x, acc0);
        acc1 = fma2(aw, wp3.y, acc1);
    }

    const float4 a1v = *(const float4*)&a1o[cq*4];
    const float4 a2v = *(const float4*)&a2o[cq*4];
    float2 v0 = unpack2(acc0);
    float2 v1 = unpack2(acc1);
    *(float4*)&g_h2[(size_t)row*CC + cq*4] = make_float4(v0.x, v0.y, v1.x, v1.y);
    float s1 = v0.x*a1v.x + v0.y*a1v.y + v1.x*a1v.z + v1.y*a1v.w;
    float s2 = v0.x*a2v.x + v0.y*a2v.y + v1.x*a2v.z + v1.y*a2v.w;
    s1 += __shfl_xor_sync(0xffffffffu, s1, 1);
    s1 += __shfl_xor_sync(0xffffffffu, s1, 2);
    s2 += __shfl_xor_sync(0xffffffffu, s2, 1);
    s2 += __shfl_xor_sync(0xffffffffu, s2, 2);
    if (cq == 0){ g_f1b[row] = s1; g_f2b[row] = s2; }
    float mx = s2;
    mx = fmaxf(mx, __shfl_xor_sync(0xffffffffu, mx, 4));
    mx = fmaxf(mx, __shfl_xor_sync(0xffffffffu, mx, 8));
    mx = fmaxf(mx, __shfl_xor_sync(0xffffffffu, mx, 16));
    if ((tid & 31) == 0) wmax2[tid >> 5] = mx;
    __syncthreads();
    if (tid == 0){
        float mm = wmax2[0];
#pragma unroll
        for (int i = 1; i < 8; i++) mm = fmaxf(mm, wmax2[i]);
        atomicMax(&g_f2bmaxu[blockIdx.x >> 3], fenc(mm));
    }
}

// ---------------- kernel 5: mma.sync attention L2 ----------------
__global__ __launch_bounds__(256, 2) void mma_attn2_kernel(float* __restrict__ out){
    __shared__ float2 ab[NN];
    __shared__ __align__(16) unsigned short Vt[JB*24];

    const int tid  = threadIdx.x;
    const int lane = tid & 31;
    const int wid  = tid >> 5;
    const int b = blockIdx.y;
    const int q0 = blockIdx.x * 128;
    const int g  = lane >> 2;
    const int jb = (lane & 3) * 2;

    {
        float v0 = g_f2b[b*NN + tid];
        float v1 = g_f2b[b*NN + tid + 256];
        ab[tid]       = make_float2(__expf(v0), __expf(LALPHA*v0));
        ab[tid + 256] = make_float2(__expf(v1), __expf(LALPHA*v1));
    }

    const int qlo = q0 + wid*16 + g;
    const int qhi = qlo + 8;
    const float fmx = fdec(g_f2bmaxu[b]);
    const float f1lo = g_f1b[b*NN + qlo];
    const float f1hi = g_f1b[b*NN + qhi];
    float s;
    s = f1lo + fmx; const float Mlo = fmaxf(s, LALPHA*s);
    s = f1hi + fmx; const float Mhi = fmaxf(s, LALPHA*s);
    const float Clo = __expf(f1lo - Mlo), Dlo = __expf(LALPHA*f1lo - Mlo);
    const float Chi = __expf(f1hi - Mhi), Dhi = __expf(LALPHA*f1hi - Mhi);
    const float eflo = g_rowempty[b*NN + qlo] ? 1.f : 0.f;
    const float efhi = g_rowempty[b*NN + qhi] ? 1.f : 0.f;

    const unsigned vt_b = sm32(Vt);
    const int jjb = ((lane >> 3) & 1)*8 + (lane & 7);
    const unsigned abase = vt_b + (unsigned)(jjb*48) + (unsigned)((lane >> 4) << 4);

    float acc[2][4];
    acc[0][0]=0.f; acc[0][1]=0.f; acc[0][2]=0.f; acc[0][3]=0.f;
    acc[1][0]=0.f; acc[1][1]=0.f; acc[1][2]=0.f; acc[1][3]=0.f;
    float lsum[4] = {0.f, 0.f, 0.f, 0.f};

    for (int t = 0; t < 4; t++){
        const int j0 = t * JB;
        __syncthreads();
#pragma unroll
        for (int i = 0; i < 4; i++){
            int lin = tid + i*256;
            int jj = lin >> 3;
            int fp = lin & 7;
            float2 v = *(const float2*)&g_h2[(size_t)(b*NN + j0 + jj)*CC + fp*2];
            *(unsigned*)((char*)Vt + jj*48 + fp*4) = cvt2h(v.x, v.y);
        }
        __syncthreads();

        uint4 m4l = *(const uint4*)&g_mask[(b*NN + qlo)*16 + t*4];
        uint4 m4h = *(const uint4*)&g_mask[(b*NN + qhi)*16 + t*4];
        unsigned mwl[4] = {m4l.x >> jb, m4l.y >> jb, m4l.z >> jb, m4l.w >> jb};
        unsigned mwh[4] = {m4h.x >> jb, m4h.y >> jb, m4h.z >> jb, m4h.w >> jb};

#pragma unroll
        for (int kk = 0; kk < 8; kk++){
            float4 u01 = *(const float4*)&ab[j0 + kk*16 + jb];
            float4 u89 = *(const float4*)&ab[j0 + kk*16 + jb + 8];
            unsigned ah[4];
            {
                unsigned w = mwl[kk>>1] >> ((kk&1)<<4);
                float p0 = fmaxf(u01.x*Clo, u01.y*Dlo);
                float p1 = fmaxf(u01.z*Clo, u01.w*Dlo);
                float p8 = fmaxf(u89.x*Clo, u89.y*Dlo);
                float p9 = fmaxf(u89.z*Clo, u89.w*Dlo);
                p0 = (w & 1u)        ? p0 : eflo;
                p1 = (w & 2u)        ? p1 : eflo;
                p8 = ((w >> 8) & 1u) ? p8 : eflo;
                p9 = ((w >> 9) & 1u) ? p9 : eflo;
                ah[0] = cvt2h(p0, p1);
                ah[2] = cvt2h(p8, p9);
            }
            {
                unsigned w = mwh[kk>>1] >> ((kk&1)<<4);
                float p0 = fmaxf(u01.x*Chi, u01.y*Dhi);
                float p1 = fmaxf(u01.z*Chi, u01.w*Dhi);
                float p8 = fmaxf(u89.x*Chi, u89.y*Dhi);
                float p9 = fmaxf(u89.z*Chi, u89.w*Dhi);
                p0 = (w & 1u)        ? p0 : efhi;
                p1 = (w & 2u)        ? p1 : efhi;
                p8 = ((w >> 8) & 1u) ? p8 : efhi;
                p9 = ((w >> 9) & 1u) ? p9 : efhi;
                ah[1] = cvt2h(p0, p1);
                ah[3] = cvt2h(p8, p9);
            }

            mma16816h(lsum, ah, ONE2, ONE2);

            unsigned b0, b1, b2, b3;
            ldsm4t(b0, b1, b2, b3, abase + (unsigned)(kk*768));
            mma16816h(acc[0], ah, b0, b1);
            mma16816h(acc[1], ah, b2, b3);
        }
    }

    const float rlo = 1.0f / lsum[0];
    const float rhi = 1.0f / lsum[2];
    float* olo = &out[(size_t)(b*NN + qlo)*CC];
    float* ohi = &out[(size_t)(b*NN + qhi)*CC];
#pragma unroll
    for (int nt = 0; nt < 2; nt++){
        int fo = nt*8 + jb;
        float2 u = make_float2(acc[nt][0]*rlo, acc[nt][1]*rlo);
        float2 v = make_float2(acc[nt][2]*rhi, acc[nt][3]*rhi);
        *(float2*)&olo[fo] = u;
        *(float2*)&ohi[fo] = v;
    }
}

// ---------------- launch ----------------
extern "C" void kernel_launch(void* const* d_in, const int* in_sizes, int n_in,
                              void* d_out, int out_size){
    const float* x   = (const float*)d_in[0];
    const int*   adj = (const int*)  d_in[1];
    const float* Wh  = (const float*)d_in[2];
    const float* a1h = (const float*)d_in[3];
    const float* a2h = (const float*)d_in[4];
    const float* Wo  = (const float*)d_in[5];
    const float* a1o = (const float*)d_in[6];
    const float* a2o = (const float*)d_in[7];
    float* out = (float*)d_out;

    fused_pack_proj_kernel<<<PROJ_BLOCKS + PACK_BLOCKS, 256>>>(adj, x, Wh, a1h, a2h); // 1
    emptyrow_kernel<<<64, 256>>>();                         // 2
    mma_attn1_kernel<<<dim3(4, BB, NH), 256>>>();           // 3
    proj2_kernel<<<256, 256>>>(Wo, a1o, a2o);               // 4  <- profiled slot
    mma_attn2_kernel<<<dim3(4, BB), 256>>>(out);            // 5
}